// round 12
// baseline (speedup 1.0000x reference)
#include <cuda_runtime.h>
#include <cstdint>
#include <cstddef>

#define TT  8
#define NN  10000
#define FIN 128
#define HD  64
#define EE  160000
#define G4  (4*HD)          // 256 gate rows

// ---------------- scratch (static device globals; no allocation) -------------
__device__ float g_xw  [TT*NN*HD];        // x @ W_gcn            (20.5 MB)
__device__ float g_dinv[TT*NN];           // deg -> 1/sqrt(deg)   (0.3 MB)
__device__ float g_agg [TT*NN*HD];        // scattered GCN output (20.5 MB)
__device__ float g_gin [TT*G4*NN];        // input gates, TRANSPOSED [t][row][n]

// ---------------- helpers -----------------------------------------------------
__device__ __forceinline__ unsigned long long fma2(unsigned long long a,
                                                   unsigned long long b,
                                                   unsigned long long c) {
    unsigned long long d;
    asm("fma.rn.f32x2 %0, %1, %2, %3;" : "=l"(d) : "l"(a), "l"(b), "l"(c));
    return d;
}
__device__ __forceinline__ unsigned long long add2(unsigned long long a,
                                                   unsigned long long b) {
    unsigned long long d;
    asm("add.rn.f32x2 %0, %1, %2;" : "=l"(d) : "l"(a), "l"(b));
    return d;
}
__device__ __forceinline__ unsigned long long pack2(float lo, float hi) {
    unsigned long long p;
    asm("mov.b64 %0, {%1, %2};" : "=l"(p) : "f"(lo), "f"(hi));
    return p;
}
__device__ __forceinline__ float2 unpack2(unsigned long long p) {
    float lo, hi;
    asm("mov.b64 {%0, %1}, %2;" : "=f"(lo), "=f"(hi) : "l"(p));
    return make_float2(lo, hi);
}
__device__ __forceinline__ int clampN(int v) {
    return v < 0 ? 0 : (v >= NN ? NN - 1 : v);
}
// named barrier over 256 threads (8 warps); ids 1,2 (0 is the CTA barrier)
__device__ __forceinline__ void bar_named(int id) {
    asm volatile("bar.sync %0, 256;" :: "r"(id) : "memory");
}

// ---------------- GCN phase ---------------------------------------------------
// edge_index is int32 (JAX x64-disabled downcasts jnp.int64 -> int32).

__global__ void count_kernel(const int* __restrict__ ei) {
    int idx = blockIdx.x * 256 + threadIdx.x;
    if (idx >= TT * EE) return;
    int t = idx / EE;
    int e = idx - t * EE;
    int dst = clampN(ei[(size_t)t * 2 * EE + EE + e]);
    atomicAdd(&g_dinv[t * NN + dst], 1.0f);
}

__global__ void dinv_kernel() {
    int i = blockIdx.x * 256 + threadIdx.x;
    if (i >= TT * NN) return;
    g_dinv[i] = rsqrtf(1.0f + g_dinv[i]);
}

// xw = x @ W_gcn : 8 rows / block, W in smem
__global__ void xw_kernel(const float* __restrict__ x, const float* __restrict__ Wg) {
    __shared__ float Ws[FIN * HD];   // 32 KB
    __shared__ float xs[8][FIN];     // 4 KB
    int tid  = threadIdx.x;          // 512 threads
    int row0 = blockIdx.x * 8;
    for (int i = tid; i < FIN * HD; i += 512) Ws[i] = Wg[i];
    for (int i = tid; i < 8 * FIN;  i += 512)
        xs[i >> 7][i & 127] = x[(size_t)(row0 + (i >> 7)) * FIN + (i & 127)];
    __syncthreads();
    int r = tid >> 6, j = tid & 63;
    float acc = 0.0f;
#pragma unroll 16
    for (int k = 0; k < FIN; k++) acc = fmaf(xs[r][k], Ws[k * HD + j], acc);
    g_xw[(size_t)(row0 + r) * HD + j] = acc;
}

// scatter: agg[dst] += xw[src] * dinv[src]*dinv[dst], vectorized red.v4
__global__ void scatter_kernel(const int* __restrict__ ei) {
    int idx = blockIdx.x * 256 + threadIdx.x;        // T*E*16 threads
    int eg  = idx >> 4;
    int c   = idx & 15;
    int t   = eg / EE;
    int e   = eg - t * EE;
    int src = clampN(ei[(size_t)t * 2 * EE + e]);
    int dst = clampN(ei[(size_t)t * 2 * EE + EE + e]);
    float norm = g_dinv[t * NN + src] * g_dinv[t * NN + dst];
    const float4 v = *(const float4*)&g_xw[((size_t)t * NN + src) * HD + c * 4];
    float4 s = make_float4(v.x * norm, v.y * norm, v.z * norm, v.w * norm);
    float* p = &g_agg[((size_t)t * NN + dst) * HD + c * 4];
    asm volatile("red.global.add.v4.f32 [%0], {%1,%2,%3,%4};"
                 :: "l"(p), "f"(s.x), "f"(s.y), "f"(s.z), "f"(s.w) : "memory");
}

// gin = relu(agg + self_loop + b_gcn) @ W_ih^T + (b_ih + b_hh)
// 32 (t,n)-rows per block; OUTPUT IS TRANSPOSED: g_gin[t][gate_row][n].
__global__ void gin_kernel(const float* __restrict__ Wih, const float* __restrict__ bgcn,
                           const float* __restrict__ bih, const float* __restrict__ bhh) {
    __shared__ float as[32][HD];      // 8 KB
    __shared__ float sg[G4][33];      // 33 KB, padded (conflict-free transpose)
    int tid  = threadIdx.x;           // 256 threads
    int row0 = blockIdx.x * 32;       // global (t,n) row base
    for (int i = tid; i < 32 * HD; i += 256) {
        int r = i >> 6, k = i & 63;
        int rg = row0 + r;
        float dv = g_dinv[rg];
        float v = g_agg[(size_t)rg * HD + k] + g_xw[(size_t)rg * HD + k] * dv * dv + bgcn[k];
        as[r][k] = fmaxf(v, 0.0f);
    }
    __syncthreads();
    int j = tid;                      // gate row 0..255
    float w[HD];
    const float4* wp = (const float4*)(Wih + (size_t)j * HD);
#pragma unroll
    for (int q = 0; q < 16; q++) {
        float4 v = __ldg(wp + q);
        w[4*q] = v.x; w[4*q+1] = v.y; w[4*q+2] = v.z; w[4*q+3] = v.w;
    }
    float bias = bih[j] + bhh[j];
#pragma unroll 4
    for (int r = 0; r < 32; r++) {
        float a_ = bias;
        const float4* av = (const float4*)&as[r][0];
#pragma unroll
        for (int q = 0; q < 16; q++) {
            float4 h4 = av[q];
            a_ = fmaf(h4.x, w[4*q],   a_);
            a_ = fmaf(h4.y, w[4*q+1], a_);
            a_ = fmaf(h4.z, w[4*q+2], a_);
            a_ = fmaf(h4.w, w[4*q+3], a_);
        }
        sg[j][r] = a_;
    }
    __syncthreads();
    int wix  = tid >> 5;
    int lane = tid & 31;
    int rg   = row0 + lane;
    int tt_  = rg / NN;
    int nn_  = rg - tt_ * NN;
#pragma unroll 4
    for (int jj = 0; jj < 32; jj++) {
        int jr = wix * 32 + jj;
        g_gin[((size_t)tt_ * G4 + jr) * NN + nn_] = sg[jr][lane];
    }
}

// ---------------- LSTM scan: 2 independent t-streams per CTA ------------------
// 512 threads = 2 groups x 8 warps. Group g handles t = blockIdx.x*2 + g with
// the R7 layout: warp w owns units w*8..w*8+7; lane: gate=lane>>3, hl=lane&7.
// Groups synchronize with DISTINCT named barriers (ids 1,2) so they drift out
// of phase: one group's serial tail overlaps the other's dot issue on the
// same SMSPs (4 warps/SMSP).
__global__ void __launch_bounds__(512, 1)
lstm_kernel(const float* __restrict__ Whh, float* __restrict__ out) {
    __shared__ __align__(16) float hbuf[2][2][HD];   // [group][buf][HD]

    int tid   = threadIdx.x;         // 0..511
    int grp   = tid >> 8;            // 0 or 1
    int ltid  = tid & 255;           // id within group
    int t     = blockIdx.x * 2 + grp;
    int wix   = ltid >> 5;           // warp-in-group 0..7
    int lane  = ltid & 31;
    int gate  = lane >> 3;
    int hl    = lane & 7;
    int hh    = wix * 8 + hl;
    int rrow  = gate * HD + hh;
    int barid = 1 + grp;

    // activation constants: i/f/o sigmoid, g tanh
    float am = (gate == 2) ? 2.0f : 1.0f;
    float aa = (gate == 2) ? 2.0f : 1.0f;
    float ab = (gate == 2) ? -1.0f : 0.0f;

    // W_hh row pinned in registers, packed f32x2
    unsigned long long w2[32];
    {
        const ulonglong2* wp = (const ulonglong2*)(Whh + (size_t)rrow * HD);
#pragma unroll
        for (int q = 0; q < 16; q++) {
            ulonglong2 v = __ldg(wp + q);
            w2[2*q]   = v.x;
            w2[2*q+1] = v.y;
        }
    }

    if (ltid < HD) hbuf[grp][0][ltid] = 0.0f;
    bar_named(barid);

    float c = 0.0f;
    const float* gp = g_gin + ((size_t)t * G4 + rrow) * NN;  // stride 1 in n
    float* op = out + (size_t)t * NN * HD + hh;

    float4 cur = __ldg((const float4*)gp);
    float4 nxt = cur;

    for (int n0 = 0; n0 < NN; n0 += 4) {
        if (n0 + 4 < NN) nxt = __ldg((const float4*)(gp + n0 + 4));

#pragma unroll
        for (int s = 0; s < 4; s++) {
            int n = n0 + s;
            int b = s & 1;
            float ginv = (s == 0) ? cur.x : (s == 1) ? cur.y : (s == 2) ? cur.z : cur.w;

            // dot: 4 independent f32x2 chains, depth 8
            unsigned long long a0 = pack2(ginv, 0.0f);
            unsigned long long a1 = 0ull, a2 = 0ull, a3 = 0ull;
            const ulonglong2* hv = (const ulonglong2*)&hbuf[grp][b][0];
#pragma unroll
            for (int q = 0; q < 8; q++) {
                ulonglong2 p0 = hv[2*q];
                ulonglong2 p1 = hv[2*q + 1];
                a0 = fma2(p0.x, w2[4*q],     a0);
                a1 = fma2(p0.y, w2[4*q + 1], a1);
                a2 = fma2(p1.x, w2[4*q + 2], a2);
                a3 = fma2(p1.y, w2[4*q + 3], a3);
            }
            float2 fs = unpack2(add2(add2(a0, a1), add2(a2, a3)));
            float acc = fs.x + fs.y;

            // activation in-lane (parallel across all 32 lanes)
            float u   = __expf(-am * acc);
            float r_  = __fdividef(1.0f, 1.0f + u);
            float act = fmaf(aa, r_, ab);   // i/f/o: sigmoid; g: tanh

            // gather activated f,g,o onto lanes 0..7 (i is local)
            float f_ = __shfl_sync(0xffffffffu, act, hl + 8);
            float g_ = __shfl_sync(0xffffffffu, act, hl + 16);
            float o_ = __shfl_sync(0xffffffffu, act, hl + 24);

            if (lane < 8) {
                c = fmaf(f_, c, act * g_);
                float e2 = __expf(-2.0f * c);
                float th = fmaf(2.0f, __fdividef(1.0f, 1.0f + e2), -1.0f); // tanh(c)
                float h_ = o_ * th;
                op[(size_t)n * HD] = h_;
                hbuf[grp][b ^ 1][hh] = h_;
            }
            bar_named(barid);
        }
        cur = nxt;
    }
}

// ---------------- launch ------------------------------------------------------
extern "C" void kernel_launch(void* const* d_in, const int* in_sizes, int n_in,
                              void* d_out, int out_size) {
    const float* x    = (const float*)d_in[0];
    const int*   ei   = (const int*)d_in[1];     // int32
    const float* Wg   = (const float*)d_in[2];
    const float* bg   = (const float*)d_in[3];
    const float* Wih  = (const float*)d_in[4];
    const float* Whh  = (const float*)d_in[5];
    const float* bih  = (const float*)d_in[6];
    const float* bhh  = (const float*)d_in[7];
    float*       out  = (float*)d_out;

    void *p_dinv, *p_agg;
    cudaGetSymbolAddress(&p_dinv, g_dinv);
    cudaGetSymbolAddress(&p_agg,  g_agg);
    cudaMemsetAsync(p_dinv, 0, sizeof(float) * TT * NN, 0);
    cudaMemsetAsync(p_agg,  0, sizeof(float) * (size_t)TT * NN * HD, 0);

    count_kernel  <<<(TT * EE + 255) / 256, 256>>>(ei);
    dinv_kernel   <<<(TT * NN + 255) / 256, 256>>>();
    xw_kernel     <<<TT * NN / 8, 512>>>(x, Wg);
    scatter_kernel<<<(TT * EE * 16) / 256, 256>>>(ei);
    gin_kernel    <<<TT * NN / 32, 256>>>(Wih, bg, bih, bhh);
    lstm_kernel   <<<TT / 2, 512>>>(Whh, out);
}

// round 13
// speedup vs baseline: 1.5709x; 1.5709x over previous
#include <cuda_runtime.h>
#include <cstdint>
#include <cstddef>

#define TT  8
#define NN  10000
#define FIN 128
#define HD  64
#define EE  160000
#define G4  (4*HD)          // 256 gate rows

// ---------------- scratch (static device globals; no allocation) -------------
__device__ float g_xw  [TT*NN*HD];        // x @ W_gcn            (20.5 MB)
__device__ float g_dinv[TT*NN];           // deg -> 1/sqrt(deg)   (0.3 MB)
__device__ float g_agg [TT*NN*HD];        // scattered GCN output (20.5 MB)
__device__ float g_gin [TT*G4*NN];        // input gates, TRANSPOSED [t][row][n]

// ---------------- helpers -----------------------------------------------------
__device__ __forceinline__ unsigned long long fma2(unsigned long long a,
                                                   unsigned long long b,
                                                   unsigned long long c) {
    unsigned long long d;
    asm("fma.rn.f32x2 %0, %1, %2, %3;" : "=l"(d) : "l"(a), "l"(b), "l"(c));
    return d;
}
__device__ __forceinline__ unsigned long long add2(unsigned long long a,
                                                   unsigned long long b) {
    unsigned long long d;
    asm("add.rn.f32x2 %0, %1, %2;" : "=l"(d) : "l"(a), "l"(b));
    return d;
}
__device__ __forceinline__ unsigned long long pack2(float lo, float hi) {
    unsigned long long p;
    asm("mov.b64 %0, {%1, %2};" : "=l"(p) : "f"(lo), "f"(hi));
    return p;
}
__device__ __forceinline__ float2 unpack2(unsigned long long p) {
    float lo, hi;
    asm("mov.b64 {%0, %1}, %2;" : "=f"(lo), "=f"(hi) : "l"(p));
    return make_float2(lo, hi);
}
__device__ __forceinline__ int clampN(int v) {
    return v < 0 ? 0 : (v >= NN ? NN - 1 : v);
}

// ---------------- GCN phase ---------------------------------------------------
// edge_index is int32 (JAX x64-disabled downcasts jnp.int64 -> int32).
// Launch order is arranged so lstm_kernel is launch #6 (ncu -s 5 -c 1 captures it).

// launch 1: zero dinv + agg (replaces the two cudaMemsetAsync)
__global__ void zero_kernel() {
    size_t i = (size_t)blockIdx.x * 1024 + threadIdx.x;
    if (i < (size_t)TT * NN * HD) g_agg[i] = 0.0f;
    if (i < (size_t)TT * NN)      g_dinv[i] = 0.0f;
}

// launch 2: fused degree-count + x@W_gcn (independent work, one launch)
// blocks [0, CNT_BLK): count;  blocks [CNT_BLK, CNT_BLK+XW_BLK): xw
#define CNT_BLK ((TT * EE + 511) / 512)     // 2500
#define XW_BLK  (TT * NN / 8)               // 10000
__global__ void count_xw_kernel(const int* __restrict__ ei,
                                const float* __restrict__ x,
                                const float* __restrict__ Wg) {
    if (blockIdx.x < CNT_BLK) {
        int idx = blockIdx.x * 512 + threadIdx.x;
        if (idx >= TT * EE) return;
        int t = idx / EE;
        int e = idx - t * EE;
        int dst = clampN(ei[(size_t)t * 2 * EE + EE + e]);
        atomicAdd(&g_dinv[t * NN + dst], 1.0f);
        return;
    }
    __shared__ float Ws[FIN * HD];   // 32 KB
    __shared__ float xs[8][FIN];     // 4 KB
    int tid  = threadIdx.x;          // 512 threads
    int row0 = (blockIdx.x - CNT_BLK) * 8;
    for (int i = tid; i < FIN * HD; i += 512) Ws[i] = Wg[i];
    for (int i = tid; i < 8 * FIN;  i += 512)
        xs[i >> 7][i & 127] = x[(size_t)(row0 + (i >> 7)) * FIN + (i & 127)];
    __syncthreads();
    int r = tid >> 6, j = tid & 63;
    float acc = 0.0f;
#pragma unroll 16
    for (int k = 0; k < FIN; k++) acc = fmaf(xs[r][k], Ws[k * HD + j], acc);
    g_xw[(size_t)(row0 + r) * HD + j] = acc;
}

// launch 3
__global__ void dinv_kernel() {
    int i = blockIdx.x * 256 + threadIdx.x;
    if (i >= TT * NN) return;
    g_dinv[i] = rsqrtf(1.0f + g_dinv[i]);
}

// launch 4: scatter agg[dst] += xw[src] * dinv[src]*dinv[dst]
__global__ void scatter_kernel(const int* __restrict__ ei) {
    int idx = blockIdx.x * 256 + threadIdx.x;        // T*E*16 threads
    int eg  = idx >> 4;
    int c   = idx & 15;
    int t   = eg / EE;
    int e   = eg - t * EE;
    int src = clampN(ei[(size_t)t * 2 * EE + e]);
    int dst = clampN(ei[(size_t)t * 2 * EE + EE + e]);
    float norm = g_dinv[t * NN + src] * g_dinv[t * NN + dst];
    const float4 v = *(const float4*)&g_xw[((size_t)t * NN + src) * HD + c * 4];
    float4 s = make_float4(v.x * norm, v.y * norm, v.z * norm, v.w * norm);
    float* p = &g_agg[((size_t)t * NN + dst) * HD + c * 4];
    asm volatile("red.global.add.v4.f32 [%0], {%1,%2,%3,%4};"
                 :: "l"(p), "f"(s.x), "f"(s.y), "f"(s.z), "f"(s.w) : "memory");
}

// launch 5: gin = relu(agg + self_loop + b_gcn) @ W_ih^T + (b_ih+b_hh), transposed out
__global__ void gin_kernel(const float* __restrict__ Wih, const float* __restrict__ bgcn,
                           const float* __restrict__ bih, const float* __restrict__ bhh) {
    __shared__ float as[32][HD];      // 8 KB
    __shared__ float sg[G4][33];      // 33 KB, padded (conflict-free transpose)
    int tid  = threadIdx.x;           // 256 threads
    int row0 = blockIdx.x * 32;       // global (t,n) row base
    for (int i = tid; i < 32 * HD; i += 256) {
        int r = i >> 6, k = i & 63;
        int rg = row0 + r;
        float dv = g_dinv[rg];
        float v = g_agg[(size_t)rg * HD + k] + g_xw[(size_t)rg * HD + k] * dv * dv + bgcn[k];
        as[r][k] = fmaxf(v, 0.0f);
    }
    __syncthreads();
    int j = tid;                      // gate row 0..255
    float w[HD];
    const float4* wp = (const float4*)(Wih + (size_t)j * HD);
#pragma unroll
    for (int q = 0; q < 16; q++) {
        float4 v = __ldg(wp + q);
        w[4*q] = v.x; w[4*q+1] = v.y; w[4*q+2] = v.z; w[4*q+3] = v.w;
    }
    float bias = bih[j] + bhh[j];
#pragma unroll 4
    for (int r = 0; r < 32; r++) {
        float a_ = bias;
        const float4* av = (const float4*)&as[r][0];
#pragma unroll
        for (int q = 0; q < 16; q++) {
            float4 h4 = av[q];
            a_ = fmaf(h4.x, w[4*q],   a_);
            a_ = fmaf(h4.y, w[4*q+1], a_);
            a_ = fmaf(h4.z, w[4*q+2], a_);
            a_ = fmaf(h4.w, w[4*q+3], a_);
        }
        sg[j][r] = a_;
    }
    __syncthreads();
    int wix  = tid >> 5;
    int lane = tid & 31;
    int rg   = row0 + lane;
    int tt_  = rg / NN;
    int nn_  = rg - tt_ * NN;
#pragma unroll 4
    for (int jj = 0; jj < 32; jj++) {
        int jr = wix * 32 + jj;
        g_gin[((size_t)tt_ * G4 + jr) * NN + nn_] = sg[jr][lane];
    }
}

// launch 6: LSTM scan, DUAL-STREAM per CTA.
// 4 CTAs x 256 threads. CTA b runs streams t=b and t=b+4 in lockstep in the
// SAME threads: thread owns gate-row rrow for both streams, so the W_hh row
// registers (w2, 64 regs) are SHARED. The two dots per step are independent
// 8-chain FMA trees that hide each other's latency; ONE __syncthreads serves
// both streams per step. R7 lane layout: warp w owns units w*8..w*8+7;
// gate = lane>>3, hl = lane&7.
__global__ void __launch_bounds__(256, 1)
lstm_kernel(const float* __restrict__ Whh, float* __restrict__ out) {
    __shared__ __align__(16) float hbuf[2][2][HD];   // [stream][buf][HD]

    int ta   = blockIdx.x;           // stream A: t = 0..3
    int tb   = blockIdx.x + 4;       // stream B: t = 4..7
    int tid  = threadIdx.x;
    int wix  = tid >> 5;
    int lane = tid & 31;
    int gate = lane >> 3;
    int hl   = lane & 7;
    int hh   = wix * 8 + hl;
    int rrow = gate * HD + hh;

    // activation constants: i/f/o sigmoid, g tanh (unified exp form)
    float am = (gate == 2) ? 2.0f : 1.0f;
    float aa = (gate == 2) ? 2.0f : 1.0f;
    float ab = (gate == 2) ? -1.0f : 0.0f;

    // W_hh row pinned once, shared by both streams
    unsigned long long w2[32];
    {
        const ulonglong2* wp = (const ulonglong2*)(Whh + (size_t)rrow * HD);
#pragma unroll
        for (int q = 0; q < 16; q++) {
            ulonglong2 v = __ldg(wp + q);
            w2[2*q]   = v.x;
            w2[2*q+1] = v.y;
        }
    }

    if (tid < HD) { hbuf[0][0][tid] = 0.0f; hbuf[1][0][tid] = 0.0f; }
    __syncthreads();

    float ca = 0.0f, cb = 0.0f;
    const float* gpa = g_gin + ((size_t)ta * G4 + rrow) * NN;
    const float* gpb = g_gin + ((size_t)tb * G4 + rrow) * NN;
    float* opa = out + (size_t)ta * NN * HD + hh;
    float* opb = out + (size_t)tb * NN * HD + hh;

    float4 cura = __ldg((const float4*)gpa);
    float4 curb = __ldg((const float4*)gpb);
    float4 nxta = cura, nxtb = curb;

    for (int n0 = 0; n0 < NN; n0 += 4) {
        if (n0 + 4 < NN) {
            nxta = __ldg((const float4*)(gpa + n0 + 4));
            nxtb = __ldg((const float4*)(gpb + n0 + 4));
        }

#pragma unroll
        for (int s = 0; s < 4; s++) {
            int n = n0 + s;
            int b = s & 1;
            float gina = (s == 0) ? cura.x : (s == 1) ? cura.y : (s == 2) ? cura.z : cura.w;
            float ginb = (s == 0) ? curb.x : (s == 1) ? curb.y : (s == 2) ? curb.z : curb.w;

            // two independent dots (8 FMA chains total, depth 8)
            unsigned long long a0 = pack2(gina, 0.0f), a1 = 0ull, a2 = 0ull, a3 = 0ull;
            unsigned long long c0 = pack2(ginb, 0.0f), c1 = 0ull, c2 = 0ull, c3 = 0ull;
            const ulonglong2* hva = (const ulonglong2*)&hbuf[0][b][0];
            const ulonglong2* hvb = (const ulonglong2*)&hbuf[1][b][0];
#pragma unroll
            for (int q = 0; q < 8; q++) {
                ulonglong2 pa0 = hva[2*q];
                ulonglong2 pa1 = hva[2*q + 1];
                ulonglong2 pb0 = hvb[2*q];
                ulonglong2 pb1 = hvb[2*q + 1];
                a0 = fma2(pa0.x, w2[4*q],     a0);
                a1 = fma2(pa0.y, w2[4*q + 1], a1);
                a2 = fma2(pa1.x, w2[4*q + 2], a2);
                a3 = fma2(pa1.y, w2[4*q + 3], a3);
                c0 = fma2(pb0.x, w2[4*q],     c0);
                c1 = fma2(pb0.y, w2[4*q + 1], c1);
                c2 = fma2(pb1.x, w2[4*q + 2], c2);
                c3 = fma2(pb1.y, w2[4*q + 3], c3);
            }
            float2 fsa = unpack2(add2(add2(a0, a1), add2(a2, a3)));
            float2 fsb = unpack2(add2(add2(c0, c1), add2(c2, c3)));
            float accA = fsa.x + fsa.y;
            float accB = fsb.x + fsb.y;

            // activations in-lane (both streams; independent MUFU chains)
            float uA   = __expf(-am * accA);
            float actA = fmaf(aa, __fdividef(1.0f, 1.0f + uA), ab);
            float uB   = __expf(-am * accB);
            float actB = fmaf(aa, __fdividef(1.0f, 1.0f + uB), ab);

            // gather f,g,o onto lanes 0..7 (i is local) for both streams
            float fA = __shfl_sync(0xffffffffu, actA, hl + 8);
            float gA = __shfl_sync(0xffffffffu, actA, hl + 16);
            float oA = __shfl_sync(0xffffffffu, actA, hl + 24);
            float fB = __shfl_sync(0xffffffffu, actB, hl + 8);
            float gB = __shfl_sync(0xffffffffu, actB, hl + 16);
            float oB = __shfl_sync(0xffffffffu, actB, hl + 24);

            if (lane < 8) {
                ca = fmaf(fA, ca, actA * gA);
                cb = fmaf(fB, cb, actB * gB);
                float eA = __expf(-2.0f * ca);
                float eB = __expf(-2.0f * cb);
                float tA = fmaf(2.0f, __fdividef(1.0f, 1.0f + eA), -1.0f);
                float tB = fmaf(2.0f, __fdividef(1.0f, 1.0f + eB), -1.0f);
                float hA = oA * tA;
                float hB = oB * tB;
                opa[(size_t)n * HD] = hA;
                opb[(size_t)n * HD] = hB;
                hbuf[0][b ^ 1][hh] = hA;
                hbuf[1][b ^ 1][hh] = hB;
            }
            __syncthreads();
        }
        cura = nxta;
        curb = nxtb;
    }
}

// ---------------- launch ------------------------------------------------------
extern "C" void kernel_launch(void* const* d_in, const int* in_sizes, int n_in,
                              void* d_out, int out_size) {
    const float* x    = (const float*)d_in[0];
    const int*   ei   = (const int*)d_in[1];     // int32
    const float* Wg   = (const float*)d_in[2];
    const float* bg   = (const float*)d_in[3];
    const float* Wih  = (const float*)d_in[4];
    const float* Whh  = (const float*)d_in[5];
    const float* bih  = (const float*)d_in[6];
    const float* bhh  = (const float*)d_in[7];
    float*       out  = (float*)d_out;

    zero_kernel    <<<(TT * NN * HD + 1023) / 1024, 1024>>>();               // 1
    count_xw_kernel<<<CNT_BLK + XW_BLK, 512>>>(ei, x, Wg);                   // 2
    dinv_kernel    <<<(TT * NN + 255) / 256, 256>>>();                       // 3
    scatter_kernel <<<(TT * EE * 16) / 256, 256>>>(ei);                      // 4
    gin_kernel     <<<TT * NN / 32, 256>>>(Wih, bg, bih, bhh);               // 5
    lstm_kernel    <<<TT / 2, 256>>>(Whh, out);                              // 6  <- ncu -s 5
}

// round 14
// speedup vs baseline: 1.7309x; 1.1019x over previous
#include <cuda_runtime.h>
#include <cstdint>
#include <cstddef>

#define TT  8
#define NN  10000
#define FIN 128
#define HD  64
#define EE  160000
#define G4  (4*HD)          // 256 gate rows

// ---------------- scratch (static device globals; no allocation) -------------
__device__ float g_xw  [TT*NN*HD];        // x @ W_gcn            (20.5 MB)
__device__ float g_dinv[TT*NN];           // deg -> 1/sqrt(deg)   (0.3 MB)
__device__ float g_agg [TT*NN*HD];        // scattered GCN output (20.5 MB)
__device__ float g_gin [TT*G4*NN];        // input gates, TRANSPOSED [t][row][n]

// ---------------- helpers -----------------------------------------------------
__device__ __forceinline__ unsigned long long fma2(unsigned long long a,
                                                   unsigned long long b,
                                                   unsigned long long c) {
    unsigned long long d;
    asm("fma.rn.f32x2 %0, %1, %2, %3;" : "=l"(d) : "l"(a), "l"(b), "l"(c));
    return d;
}
__device__ __forceinline__ unsigned long long add2(unsigned long long a,
                                                   unsigned long long b) {
    unsigned long long d;
    asm("add.rn.f32x2 %0, %1, %2;" : "=l"(d) : "l"(a), "l"(b));
    return d;
}
__device__ __forceinline__ unsigned long long pack2(float lo, float hi) {
    unsigned long long p;
    asm("mov.b64 %0, {%1, %2};" : "=l"(p) : "f"(lo), "f"(hi));
    return p;
}
__device__ __forceinline__ float2 unpack2(unsigned long long p) {
    float lo, hi;
    asm("mov.b64 {%0, %1}, %2;" : "=f"(lo), "=f"(hi) : "l"(p));
    return make_float2(lo, hi);
}
__device__ __forceinline__ float ftanh_hw(float x) {   // single MUFU op
    float y;
    asm("tanh.approx.f32 %0, %1;" : "=f"(y) : "f"(x));
    return y;
}
__device__ __forceinline__ int clampN(int v) {
    return v < 0 ? 0 : (v >= NN ? NN - 1 : v);
}

// ---------------- GCN phase ---------------------------------------------------
// edge_index is int32 (JAX x64-disabled downcasts jnp.int64 -> int32).

// zero dinv + agg (replaces cudaMemsetAsync)
__global__ void zero_kernel() {
    size_t i = (size_t)blockIdx.x * 1024 + threadIdx.x;
    if (i < (size_t)TT * NN * HD) g_agg[i] = 0.0f;
    if (i < (size_t)TT * NN)      g_dinv[i] = 0.0f;
}

// fused degree-count + x@W_gcn
#define CNT_BLK ((TT * EE + 511) / 512)     // 2500
#define XW_BLK  (TT * NN / 8)               // 10000
__global__ void count_xw_kernel(const int* __restrict__ ei,
                                const float* __restrict__ x,
                                const float* __restrict__ Wg) {
    if (blockIdx.x < CNT_BLK) {
        int idx = blockIdx.x * 512 + threadIdx.x;
        if (idx >= TT * EE) return;
        int t = idx / EE;
        int e = idx - t * EE;
        int dst = clampN(ei[(size_t)t * 2 * EE + EE + e]);
        atomicAdd(&g_dinv[t * NN + dst], 1.0f);
        return;
    }
    __shared__ float Ws[FIN * HD];   // 32 KB
    __shared__ float xs[8][FIN];     // 4 KB
    int tid  = threadIdx.x;          // 512 threads
    int row0 = (blockIdx.x - CNT_BLK) * 8;
    for (int i = tid; i < FIN * HD; i += 512) Ws[i] = Wg[i];
    for (int i = tid; i < 8 * FIN;  i += 512)
        xs[i >> 7][i & 127] = x[(size_t)(row0 + (i >> 7)) * FIN + (i & 127)];
    __syncthreads();
    int r = tid >> 6, j = tid & 63;
    float acc = 0.0f;
#pragma unroll 16
    for (int k = 0; k < FIN; k++) acc = fmaf(xs[r][k], Ws[k * HD + j], acc);
    g_xw[(size_t)(row0 + r) * HD + j] = acc;
}

__global__ void dinv_kernel() {
    int i = blockIdx.x * 256 + threadIdx.x;
    if (i >= TT * NN) return;
    g_dinv[i] = rsqrtf(1.0f + g_dinv[i]);
}

// scatter: agg[dst] += xw[src] * dinv[src]*dinv[dst], vectorized red.v4
__global__ void scatter_kernel(const int* __restrict__ ei) {
    int idx = blockIdx.x * 256 + threadIdx.x;        // T*E*16 threads
    int eg  = idx >> 4;
    int c   = idx & 15;
    int t   = eg / EE;
    int e   = eg - t * EE;
    int src = clampN(ei[(size_t)t * 2 * EE + e]);
    int dst = clampN(ei[(size_t)t * 2 * EE + EE + e]);
    float norm = g_dinv[t * NN + src] * g_dinv[t * NN + dst];
    const float4 v = *(const float4*)&g_xw[((size_t)t * NN + src) * HD + c * 4];
    float4 s = make_float4(v.x * norm, v.y * norm, v.z * norm, v.w * norm);
    float* p = &g_agg[((size_t)t * NN + dst) * HD + c * 4];
    asm volatile("red.global.add.v4.f32 [%0], {%1,%2,%3,%4};"
                 :: "l"(p), "f"(s.x), "f"(s.y), "f"(s.z), "f"(s.w) : "memory");
}

// gin = relu(agg + self_loop + b_gcn) @ W_ih^T + (b_ih+b_hh), TRANSPOSED out
__global__ void gin_kernel(const float* __restrict__ Wih, const float* __restrict__ bgcn,
                           const float* __restrict__ bih, const float* __restrict__ bhh) {
    __shared__ float as[32][HD];      // 8 KB
    __shared__ float sg[G4][33];      // 33 KB, padded (conflict-free transpose)
    int tid  = threadIdx.x;           // 256 threads
    int row0 = blockIdx.x * 32;       // global (t,n) row base
    for (int i = tid; i < 32 * HD; i += 256) {
        int r = i >> 6, k = i & 63;
        int rg = row0 + r;
        float dv = g_dinv[rg];
        float v = g_agg[(size_t)rg * HD + k] + g_xw[(size_t)rg * HD + k] * dv * dv + bgcn[k];
        as[r][k] = fmaxf(v, 0.0f);
    }
    __syncthreads();
    int j = tid;                      // gate row 0..255
    float w[HD];
    const float4* wp = (const float4*)(Wih + (size_t)j * HD);
#pragma unroll
    for (int q = 0; q < 16; q++) {
        float4 v = __ldg(wp + q);
        w[4*q] = v.x; w[4*q+1] = v.y; w[4*q+2] = v.z; w[4*q+3] = v.w;
    }
    float bias = bih[j] + bhh[j];
#pragma unroll 4
    for (int r = 0; r < 32; r++) {
        float a_ = bias;
        const float4* av = (const float4*)&as[r][0];
#pragma unroll
        for (int q = 0; q < 16; q++) {
            float4 h4 = av[q];
            a_ = fmaf(h4.x, w[4*q],   a_);
            a_ = fmaf(h4.y, w[4*q+1], a_);
            a_ = fmaf(h4.z, w[4*q+2], a_);
            a_ = fmaf(h4.w, w[4*q+3], a_);
        }
        sg[j][r] = a_;
    }
    __syncthreads();
    int wix  = tid >> 5;
    int lane = tid & 31;
    int rg   = row0 + lane;
    int tt_  = rg / NN;
    int nn_  = rg - tt_ * NN;
#pragma unroll 4
    for (int jj = 0; jj < 32; jj++) {
        int jr = wix * 32 + jj;
        g_gin[((size_t)tt_ * G4 + jr) * NN + nn_] = sg[jr][lane];
    }
}

// ---------------- LSTM scan: R7 layout + MUFU.TANH + all-lane c/h -------------
// One CTA per t. 256 threads = 8 warps; warp w owns units w*8..w*8+7.
// Lane: gate = lane>>3, hl = lane&7, unit hh = w*8+hl, row rrow = gate*HD+hh.
// Dot: 4 independent f32x2 chains with W_hh row in registers.
// Activations: y = tanh(k*acc); act = A*y + B  (sigmoid: k=A=B=0.5; tanh: k=A=1,B=0)
// -> single MUFU.TANH per gate. Then 4 shfls give every lane (i,f,g,o) of its
// unit hl; ALL lanes redundantly update c,h (no divergent compute); lanes 0..7
// do the two predicated stores.
__global__ void __launch_bounds__(256, 1)
lstm_kernel(const float* __restrict__ Whh, float* __restrict__ out) {
    __shared__ __align__(16) float hbuf[2][HD];

    int t    = blockIdx.x;
    int tid  = threadIdx.x;
    int wix  = tid >> 5;
    int lane = tid & 31;
    int gate = lane >> 3;
    int hl   = lane & 7;
    int hh   = wix * 8 + hl;
    int rrow = gate * HD + hh;

    // activation constants (unified tanh form)
    float ak = (gate == 2) ? 1.0f : 0.5f;   // pre-scale
    float aA = (gate == 2) ? 1.0f : 0.5f;   // post-scale
    float aB = (gate == 2) ? 0.0f : 0.5f;   // post-offset

    // W_hh row pinned in registers, packed f32x2
    unsigned long long w2[32];
    {
        const ulonglong2* wp = (const ulonglong2*)(Whh + (size_t)rrow * HD);
#pragma unroll
        for (int q = 0; q < 16; q++) {
            ulonglong2 v = __ldg(wp + q);
            w2[2*q]   = v.x;
            w2[2*q+1] = v.y;
        }
    }

    if (tid < HD) hbuf[0][tid] = 0.0f;
    __syncthreads();

    float c = 0.0f;                         // c for unit hh (redundant x4 across gates)
    const float* gp = g_gin + ((size_t)t * G4 + rrow) * NN;  // stride 1 in n
    float* op = out + (size_t)t * NN * HD + hh;

    float4 cur = __ldg((const float4*)gp);
    float4 nxt = cur;

    for (int n0 = 0; n0 < NN; n0 += 4) {
        if (n0 + 4 < NN) nxt = __ldg((const float4*)(gp + n0 + 4));

#pragma unroll
        for (int s = 0; s < 4; s++) {
            int n = n0 + s;
            int b = s & 1;
            float ginv = (s == 0) ? cur.x : (s == 1) ? cur.y : (s == 2) ? cur.z : cur.w;

            // dot: 4 independent f32x2 chains, depth 8
            unsigned long long a0 = pack2(ginv, 0.0f);
            unsigned long long a1 = 0ull, a2 = 0ull, a3 = 0ull;
            const ulonglong2* hv = (const ulonglong2*)&hbuf[b][0];
#pragma unroll
            for (int q = 0; q < 8; q++) {
                ulonglong2 p0 = hv[2*q];
                ulonglong2 p1 = hv[2*q + 1];
                a0 = fma2(p0.x, w2[4*q],     a0);
                a1 = fma2(p0.y, w2[4*q + 1], a1);
                a2 = fma2(p1.x, w2[4*q + 2], a2);
                a3 = fma2(p1.y, w2[4*q + 3], a3);
            }
            float2 fs = unpack2(add2(add2(a0, a1), add2(a2, a3)));
            float acc = fs.x + fs.y;

            // activation: single MUFU.TANH (sigmoid via 0.5*tanh(x/2)+0.5)
            float act = fmaf(aA, ftanh_hw(ak * acc), aB);

            // every lane collects i,f,g,o for its unit hl (4 parallel shfls)
            float i_ = __shfl_sync(0xffffffffu, act, hl);
            float f_ = __shfl_sync(0xffffffffu, act, hl + 8);
            float g_ = __shfl_sync(0xffffffffu, act, hl + 16);
            float o_ = __shfl_sync(0xffffffffu, act, hl + 24);

            // redundant c,h update in ALL lanes (no divergent compute region)
            c = fmaf(f_, c, i_ * g_);
            float h_ = o_ * ftanh_hw(c);

            if (lane < 8) {                  // predicated stores only
                op[(size_t)n * HD] = h_;
                hbuf[b ^ 1][hh] = h_;
            }
            __syncthreads();
        }
        cur = nxt;
    }
}

// ---------------- launch ------------------------------------------------------
extern "C" void kernel_launch(void* const* d_in, const int* in_sizes, int n_in,
                              void* d_out, int out_size) {
    const float* x    = (const float*)d_in[0];
    const int*   ei   = (const int*)d_in[1];     // int32
    const float* Wg   = (const float*)d_in[2];
    const float* bg   = (const float*)d_in[3];
    const float* Wih  = (const float*)d_in[4];
    const float* Whh  = (const float*)d_in[5];
    const float* bih  = (const float*)d_in[6];
    const float* bhh  = (const float*)d_in[7];
    float*       out  = (float*)d_out;

    zero_kernel    <<<(TT * NN * HD + 1023) / 1024, 1024>>>();
    count_xw_kernel<<<CNT_BLK + XW_BLK, 512>>>(ei, x, Wg);
    dinv_kernel    <<<(TT * NN + 255) / 256, 256>>>();
    scatter_kernel <<<(TT * EE * 16) / 256, 256>>>(ei);
    gin_kernel     <<<TT * NN / 32, 256>>>(Wih, bg, bih, bhh);
    lstm_kernel    <<<TT, 256>>>(Whh, out);
}

// round 15
// speedup vs baseline: 2.7034x; 1.5618x over previous
#include <cuda_runtime.h>
#include <cstdint>
#include <cstddef>

#define TT  8
#define NN  10000
#define FIN 128
#define HD  64
#define EE  160000
#define G4  (4*HD)          // 256 gate rows

// ---------------- scratch (static device globals; no allocation) -------------
__device__ float g_xw  [TT*NN*HD];        // x @ W_gcn            (20.5 MB)
__device__ float g_dinv[TT*NN];           // deg -> 1/sqrt(deg)   (0.3 MB)
__device__ float g_agg [TT*NN*HD];        // scattered GCN output (20.5 MB)
__device__ float g_gin [TT*G4*NN];        // input gates, TRANSPOSED [t][row][n]

// ---------------- helpers -----------------------------------------------------
__device__ __forceinline__ unsigned long long fma2(unsigned long long a,
                                                   unsigned long long b,
                                                   unsigned long long c) {
    unsigned long long d;
    asm("fma.rn.f32x2 %0, %1, %2, %3;" : "=l"(d) : "l"(a), "l"(b), "l"(c));
    return d;
}
__device__ __forceinline__ unsigned long long add2(unsigned long long a,
                                                   unsigned long long b) {
    unsigned long long d;
    asm("add.rn.f32x2 %0, %1, %2;" : "=l"(d) : "l"(a), "l"(b));
    return d;
}
__device__ __forceinline__ unsigned long long pack2(float lo, float hi) {
    unsigned long long p;
    asm("mov.b64 %0, {%1, %2};" : "=l"(p) : "f"(lo), "f"(hi));
    return p;
}
__device__ __forceinline__ float2 unpack2(unsigned long long p) {
    float lo, hi;
    asm("mov.b64 {%0, %1}, %2;" : "=f"(lo), "=f"(hi) : "l"(p));
    return make_float2(lo, hi);
}
__device__ __forceinline__ float ftanh_hw(float x) {   // single MUFU op
    float y;
    asm("tanh.approx.f32 %0, %1;" : "=f"(y) : "f"(x));
    return y;
}
__device__ __forceinline__ int clampN(int v) {
    return v < 0 ? 0 : (v >= NN ? NN - 1 : v);
}

// ---------------- GCN phase ---------------------------------------------------
// edge_index is int32 (JAX x64-disabled downcasts jnp.int64 -> int32).

// zero dinv + agg
__global__ void zero_kernel() {
    size_t i = (size_t)blockIdx.x * 1024 + threadIdx.x;
    if (i < (size_t)TT * NN * HD) g_agg[i] = 0.0f;
    if (i < (size_t)TT * NN)      g_dinv[i] = 0.0f;
}

// fused degree-count + x@W_gcn
#define CNT_BLK ((TT * EE + 511) / 512)     // 2500
#define XW_BLK  (TT * NN / 8)               // 10000
__global__ void count_xw_kernel(const int* __restrict__ ei,
                                const float* __restrict__ x,
                                const float* __restrict__ Wg) {
    if (blockIdx.x < CNT_BLK) {
        int idx = blockIdx.x * 512 + threadIdx.x;
        if (idx >= TT * EE) return;
        int t = idx / EE;
        int e = idx - t * EE;
        int dst = clampN(ei[(size_t)t * 2 * EE + EE + e]);
        atomicAdd(&g_dinv[t * NN + dst], 1.0f);
        return;
    }
    __shared__ float Ws[FIN * HD];   // 32 KB
    __shared__ float xs[8][FIN];     // 4 KB
    int tid  = threadIdx.x;          // 512 threads
    int row0 = (blockIdx.x - CNT_BLK) * 8;
    for (int i = tid; i < FIN * HD; i += 512) Ws[i] = Wg[i];
    for (int i = tid; i < 8 * FIN;  i += 512)
        xs[i >> 7][i & 127] = x[(size_t)(row0 + (i >> 7)) * FIN + (i & 127)];
    __syncthreads();
    int r = tid >> 6, j = tid & 63;
    float acc = 0.0f;
#pragma unroll 16
    for (int k = 0; k < FIN; k++) acc = fmaf(xs[r][k], Ws[k * HD + j], acc);
    g_xw[(size_t)(row0 + r) * HD + j] = acc;
}

__global__ void dinv_kernel() {
    int i = blockIdx.x * 256 + threadIdx.x;
    if (i >= TT * NN) return;
    g_dinv[i] = rsqrtf(1.0f + g_dinv[i]);
}

// scatter: agg[dst] += xw[src] * dinv[src]*dinv[dst], vectorized red.v4
// (unchanged every round — serves as the cross-session clock yardstick)
__global__ void scatter_kernel(const int* __restrict__ ei) {
    int idx = blockIdx.x * 256 + threadIdx.x;        // T*E*16 threads
    int eg  = idx >> 4;
    int c   = idx & 15;
    int t   = eg / EE;
    int e   = eg - t * EE;
    int src = clampN(ei[(size_t)t * 2 * EE + e]);
    int dst = clampN(ei[(size_t)t * 2 * EE + EE + e]);
    float norm = g_dinv[t * NN + src] * g_dinv[t * NN + dst];
    const float4 v = *(const float4*)&g_xw[((size_t)t * NN + src) * HD + c * 4];
    float4 s = make_float4(v.x * norm, v.y * norm, v.z * norm, v.w * norm);
    float* p = &g_agg[((size_t)t * NN + dst) * HD + c * 4];
    asm volatile("red.global.add.v4.f32 [%0], {%1,%2,%3,%4};"
                 :: "l"(p), "f"(s.x), "f"(s.y), "f"(s.z), "f"(s.w) : "memory");
}

// gin = relu(agg + self_loop + b_gcn) @ W_ih^T + (b_ih+b_hh), TRANSPOSED out
__global__ void gin_kernel(const float* __restrict__ Wih, const float* __restrict__ bgcn,
                           const float* __restrict__ bih, const float* __restrict__ bhh) {
    __shared__ float as[32][HD];      // 8 KB
    __shared__ float sg[G4][33];      // 33 KB, padded (conflict-free transpose)
    int tid  = threadIdx.x;           // 256 threads
    int row0 = blockIdx.x * 32;       // global (t,n) row base
    for (int i = tid; i < 32 * HD; i += 256) {
        int r = i >> 6, k = i & 63;
        int rg = row0 + r;
        float dv = g_dinv[rg];
        float v = g_agg[(size_t)rg * HD + k] + g_xw[(size_t)rg * HD + k] * dv * dv + bgcn[k];
        as[r][k] = fmaxf(v, 0.0f);
    }
    __syncthreads();
    int j = tid;                      // gate row 0..255
    float w[HD];
    const float4* wp = (const float4*)(Wih + (size_t)j * HD);
#pragma unroll
    for (int q = 0; q < 16; q++) {
        float4 v = __ldg(wp + q);
        w[4*q] = v.x; w[4*q+1] = v.y; w[4*q+2] = v.z; w[4*q+3] = v.w;
    }
    float bias = bih[j] + bhh[j];
#pragma unroll 4
    for (int r = 0; r < 32; r++) {
        float a_ = bias;
        const float4* av = (const float4*)&as[r][0];
#pragma unroll
        for (int q = 0; q < 16; q++) {
            float4 h4 = av[q];
            a_ = fmaf(h4.x, w[4*q],   a_);
            a_ = fmaf(h4.y, w[4*q+1], a_);
            a_ = fmaf(h4.z, w[4*q+2], a_);
            a_ = fmaf(h4.w, w[4*q+3], a_);
        }
        sg[j][r] = a_;
    }
    __syncthreads();
    int wix  = tid >> 5;
    int lane = tid & 31;
    int rg   = row0 + lane;
    int tt_  = rg / NN;
    int nn_  = rg - tt_ * NN;
#pragma unroll 4
    for (int jj = 0; jj < 32; jj++) {
        int jr = wix * 32 + jj;
        g_gin[((size_t)tt_ * G4 + jr) * NN + nn_] = sg[jr][lane];
    }
}

// ---------------- LSTM scan: 4 warps, 2 gate-rows/thread + MUFU.TANH ----------
// One CTA per t, 128 threads. Pair p = tid>>1 owns unit u=p (lanes 2u,2u+1
// of the same warp): even thread computes rows u (i) and 128+u (g);
// odd thread rows 64+u (f) and 192+u (o). h LDS.128 amortized over both rows.
// Activations: single MUFU.TANH each (sigmoid = 0.5*tanh(x/2)+0.5).
// Gate exchange: 2x shfl_xor(1). c,h redundantly computed in both pair threads
// (no divergent compute); even thread does the two predicated stores.
__global__ void __launch_bounds__(128, 1)
lstm_kernel(const float* __restrict__ Whh, float* __restrict__ out) {
    __shared__ __align__(16) float hbuf[2][HD];

    int t    = blockIdx.x;
    int tid  = threadIdx.x;          // 128
    int odd  = tid & 1;
    int u    = tid >> 1;             // hidden unit 0..63
    int rowa = odd * 64 + u;         // i (even) / f (odd)  -> always sigmoid
    int rowb = 128 + odd * 64 + u;   // g (even) / o (odd)

    // row-b activation constants: tanh (even) / sigmoid (odd); unified tanh form
    float kb = odd ? 0.5f : 1.0f;    // pre-scale
    float Ab = odd ? 0.5f : 1.0f;    // post-scale
    float Bb = odd ? 0.5f : 0.0f;    // post-offset

    // two W_hh rows pinned in registers as f32x2
    unsigned long long wa[32], wb[32];
    {
        const ulonglong2* pa = (const ulonglong2*)(Whh + (size_t)rowa * HD);
        const ulonglong2* pb = (const ulonglong2*)(Whh + (size_t)rowb * HD);
#pragma unroll
        for (int q = 0; q < 16; q++) {
            ulonglong2 va = __ldg(pa + q);
            ulonglong2 vb = __ldg(pb + q);
            wa[2*q] = va.x; wa[2*q+1] = va.y;
            wb[2*q] = vb.x; wb[2*q+1] = vb.y;
        }
    }

    if (tid < HD) hbuf[0][tid] = 0.0f;
    __syncthreads();

    float c = 0.0f;
    const float* gpa = g_gin + ((size_t)t * G4 + rowa) * NN;
    const float* gpb = g_gin + ((size_t)t * G4 + rowb) * NN;
    float* op = out + (size_t)t * NN * HD + u;

    float4 cura = __ldg((const float4*)gpa);
    float4 curb = __ldg((const float4*)gpb);
    float4 nxta = cura, nxtb = curb;

    for (int n0 = 0; n0 < NN; n0 += 4) {
        if (n0 + 4 < NN) {
            nxta = __ldg((const float4*)(gpa + n0 + 4));
            nxtb = __ldg((const float4*)(gpb + n0 + 4));
        }

#pragma unroll
        for (int s = 0; s < 4; s++) {
            int n = n0 + s;
            int b = s & 1;
            float gina = (s == 0) ? cura.x : (s == 1) ? cura.y : (s == 2) ? cura.z : cura.w;
            float ginb = (s == 0) ? curb.x : (s == 1) ? curb.y : (s == 2) ? curb.z : curb.w;

            // two dots sharing the h loads; 2 f32x2 chains per row
            unsigned long long a0 = pack2(gina, 0.0f), a1 = 0ull;
            unsigned long long b0 = pack2(ginb, 0.0f), b1 = 0ull;
            const ulonglong2* hv = (const ulonglong2*)&hbuf[b][0];
#pragma unroll
            for (int q = 0; q < 16; q++) {
                ulonglong2 p = hv[q];
                a0 = fma2(p.x, wa[2*q],     a0);
                a1 = fma2(p.y, wa[2*q + 1], a1);
                b0 = fma2(p.x, wb[2*q],     b0);
                b1 = fma2(p.y, wb[2*q + 1], b1);
            }
            float2 fa = unpack2(add2(a0, a1));
            float2 fb = unpack2(add2(b0, b1));
            float acc_a = fa.x + fa.y;
            float acc_b = fb.x + fb.y;

            // activations: one MUFU.TANH each
            float act_a = fmaf(0.5f, ftanh_hw(0.5f * acc_a), 0.5f);  // i or f (sigmoid)
            float act_b = fmaf(Ab,   ftanh_hw(kb * acc_b),   Bb);    // g or o

            // pair exchange: even(i,g) <-> odd(f,o)
            float x1 = __shfl_xor_sync(0xffffffffu, act_a, 1);
            float x2 = __shfl_xor_sync(0xffffffffu, act_b, 1);
            float i_ = odd ? x1    : act_a;
            float f_ = odd ? act_a : x1;
            float g_ = odd ? x2    : act_b;
            float o_ = odd ? act_b : x2;

            // redundant c,h in both threads of the pair
            c = fmaf(f_, c, i_ * g_);
            float h_ = o_ * ftanh_hw(c);

            if (!odd) {                      // short predicated arm: stores only
                op[(size_t)n * HD] = h_;
                hbuf[b ^ 1][u] = h_;
            }
            __syncthreads();
        }
        cura = nxta;
        curb = nxtb;
    }
}

// ---------------- launch ------------------------------------------------------
extern "C" void kernel_launch(void* const* d_in, const int* in_sizes, int n_in,
                              void* d_out, int out_size) {
    const float* x    = (const float*)d_in[0];
    const int*   ei   = (const int*)d_in[1];     // int32
    const float* Wg   = (const float*)d_in[2];
    const float* bg   = (const float*)d_in[3];
    const float* Wih  = (const float*)d_in[4];
    const float* Whh  = (const float*)d_in[5];
    const float* bih  = (const float*)d_in[6];
    const float* bhh  = (const float*)d_in[7];
    float*       out  = (float*)d_out;

    zero_kernel    <<<(TT * NN * HD + 1023) / 1024, 1024>>>();
    count_xw_kernel<<<CNT_BLK + XW_BLK, 512>>>(ei, x, Wg);
    dinv_kernel    <<<(TT * NN + 255) / 256, 256>>>();
    scatter_kernel <<<(TT * EE * 16) / 256, 256>>>(ei);
    gin_kernel     <<<TT * NN / 32, 256>>>(Wih, bg, bih, bhh);
    lstm_kernel    <<<TT, 128>>>(Whh, out);
}

// round 16
// speedup vs baseline: 2.9563x; 1.0935x over previous
#include <cuda_runtime.h>
#include <cstdint>
#include <cstddef>

#define TT  8
#define NN  10000
#define FIN 128
#define HD  64
#define EE  160000
#define G4  (4*HD)          // 256 gate rows

// ---------------- scratch (static device globals; no allocation) -------------
__device__ float g_xw  [TT*NN*HD];        // x @ W_gcn            (20.5 MB)
__device__ float g_dinv[TT*NN];           // deg -> 1/sqrt(deg)   (0.3 MB)
__device__ float g_agg [TT*NN*HD];        // scattered GCN output (20.5 MB)
__device__ float g_gin [TT*G4*NN];        // input gates, TRANSPOSED [t][row][n]

// ---------------- helpers -----------------------------------------------------
__device__ __forceinline__ unsigned long long fma2(unsigned long long a,
                                                   unsigned long long b,
                                                   unsigned long long c) {
    unsigned long long d;
    asm("fma.rn.f32x2 %0, %1, %2, %3;" : "=l"(d) : "l"(a), "l"(b), "l"(c));
    return d;
}
__device__ __forceinline__ unsigned long long add2(unsigned long long a,
                                                   unsigned long long b) {
    unsigned long long d;
    asm("add.rn.f32x2 %0, %1, %2;" : "=l"(d) : "l"(a), "l"(b));
    return d;
}
__device__ __forceinline__ unsigned long long pack2(float lo, float hi) {
    unsigned long long p;
    asm("mov.b64 %0, {%1, %2};" : "=l"(p) : "f"(lo), "f"(hi));
    return p;
}
__device__ __forceinline__ float2 unpack2(unsigned long long p) {
    float lo, hi;
    asm("mov.b64 {%0, %1}, %2;" : "=f"(lo), "=f"(hi) : "l"(p));
    return make_float2(lo, hi);
}
__device__ __forceinline__ float ftanh_hw(float x) {   // single MUFU op
    float y;
    asm("tanh.approx.f32 %0, %1;" : "=f"(y) : "f"(x));
    return y;
}
__device__ __forceinline__ int clampN(int v) {
    return v < 0 ? 0 : (v >= NN ? NN - 1 : v);
}

// ---------------- GCN phase ---------------------------------------------------
// edge_index is int32 (JAX x64-disabled downcasts jnp.int64 -> int32).

// launch 1: zero dinv only (tiny; agg zeroing folded into dinv_kernel)
__global__ void zero_dinv_kernel() {
    int i = blockIdx.x * 256 + threadIdx.x;
    if (i < TT * NN) g_dinv[i] = 0.0f;
}

// launch 2: fused degree-count + x@W_gcn
#define CNT_BLK ((TT * EE + 511) / 512)     // 2500
#define XW_BLK  (TT * NN / 8)               // 10000
__global__ void count_xw_kernel(const int* __restrict__ ei,
                                const float* __restrict__ x,
                                const float* __restrict__ Wg) {
    if (blockIdx.x < CNT_BLK) {
        int idx = blockIdx.x * 512 + threadIdx.x;
        if (idx >= TT * EE) return;
        int t = idx / EE;
        int e = idx - t * EE;
        int dst = clampN(ei[(size_t)t * 2 * EE + EE + e]);
        atomicAdd(&g_dinv[t * NN + dst], 1.0f);
        return;
    }
    __shared__ float Ws[FIN * HD];   // 32 KB
    __shared__ float xs[8][FIN];     // 4 KB
    int tid  = threadIdx.x;          // 512 threads
    int row0 = (blockIdx.x - CNT_BLK) * 8;
    for (int i = tid; i < FIN * HD; i += 512) Ws[i] = Wg[i];
    for (int i = tid; i < 8 * FIN;  i += 512)
        xs[i >> 7][i & 127] = x[(size_t)(row0 + (i >> 7)) * FIN + (i & 127)];
    __syncthreads();
    int r = tid >> 6, j = tid & 63;
    float acc = 0.0f;
#pragma unroll 16
    for (int k = 0; k < FIN; k++) acc = fmaf(xs[r][k], Ws[k * HD + j], acc);
    g_xw[(size_t)(row0 + r) * HD + j] = acc;
}

// launch 3: dinv = rsqrt(1+deg), and zero g_agg (grid-stride float4)
#define DZ_BLK 5120
__global__ void dinv_zero_kernel() {
    int i = blockIdx.x * 256 + threadIdx.x;
    if (i < TT * NN) g_dinv[i] = rsqrtf(1.0f + g_dinv[i]);
    float4 z = make_float4(0.f, 0.f, 0.f, 0.f);
    for (size_t j = i; j < (size_t)TT * NN * HD / 4; j += (size_t)DZ_BLK * 256)
        ((float4*)g_agg)[j] = z;
}

// launch 4: scatter agg[dst] += xw[src]*dinv[src]*dinv[dst]  (clock yardstick)
__global__ void scatter_kernel(const int* __restrict__ ei) {
    int idx = blockIdx.x * 256 + threadIdx.x;        // T*E*16 threads
    int eg  = idx >> 4;
    int c   = idx & 15;
    int t   = eg / EE;
    int e   = eg - t * EE;
    int src = clampN(ei[(size_t)t * 2 * EE + e]);
    int dst = clampN(ei[(size_t)t * 2 * EE + EE + e]);
    float norm = g_dinv[t * NN + src] * g_dinv[t * NN + dst];
    const float4 v = *(const float4*)&g_xw[((size_t)t * NN + src) * HD + c * 4];
    float4 s = make_float4(v.x * norm, v.y * norm, v.z * norm, v.w * norm);
    float* p = &g_agg[((size_t)t * NN + dst) * HD + c * 4];
    asm volatile("red.global.add.v4.f32 [%0], {%1,%2,%3,%4};"
                 :: "l"(p), "f"(s.x), "f"(s.y), "f"(s.z), "f"(s.w) : "memory");
}

// launch 5: gin = relu(agg + self_loop + b_gcn) @ W_ih^T + (b_ih+b_hh), transposed
__global__ void gin_kernel(const float* __restrict__ Wih, const float* __restrict__ bgcn,
                           const float* __restrict__ bih, const float* __restrict__ bhh) {
    __shared__ float as[32][HD];      // 8 KB
    __shared__ float sg[G4][33];      // 33 KB, padded (conflict-free transpose)
    int tid  = threadIdx.x;           // 256 threads
    int row0 = blockIdx.x * 32;       // global (t,n) row base
    for (int i = tid; i < 32 * HD; i += 256) {
        int r = i >> 6, k = i & 63;
        int rg = row0 + r;
        float dv = g_dinv[rg];
        float v = g_agg[(size_t)rg * HD + k] + g_xw[(size_t)rg * HD + k] * dv * dv + bgcn[k];
        as[r][k] = fmaxf(v, 0.0f);
    }
    __syncthreads();
    int j = tid;                      // gate row 0..255
    float w[HD];
    const float4* wp = (const float4*)(Wih + (size_t)j * HD);
#pragma unroll
    for (int q = 0; q < 16; q++) {
        float4 v = __ldg(wp + q);
        w[4*q] = v.x; w[4*q+1] = v.y; w[4*q+2] = v.z; w[4*q+3] = v.w;
    }
    float bias = bih[j] + bhh[j];
#pragma unroll 4
    for (int r = 0; r < 32; r++) {
        float a_ = bias;
        const float4* av = (const float4*)&as[r][0];
#pragma unroll
        for (int q = 0; q < 16; q++) {
            float4 h4 = av[q];
            a_ = fmaf(h4.x, w[4*q],   a_);
            a_ = fmaf(h4.y, w[4*q+1], a_);
            a_ = fmaf(h4.z, w[4*q+2], a_);
            a_ = fmaf(h4.w, w[4*q+3], a_);
        }
        sg[j][r] = a_;
    }
    __syncthreads();
    int wix  = tid >> 5;
    int lane = tid & 31;
    int rg   = row0 + lane;
    int tt_  = rg / NN;
    int nn_  = rg - tt_ * NN;
#pragma unroll 4
    for (int jj = 0; jj < 32; jj++) {
        int jr = wix * 32 + jj;
        g_gin[((size_t)tt_ * G4 + jr) * NN + nn_] = sg[jr][lane];
    }
}

// launch 6: LSTM scan — R15 winner + shortened exchange tail.
// One CTA per t, 128 threads. Pair p = tid>>1 owns unit u=p (lanes 2u,2u+1):
//   even thread rows u (i) and 128+u (g); odd rows 64+u (f) and 192+u (o).
// Product-exchange: even computes ig=i*g locally; shfl1 swaps ig<->f,
// shfl2 swaps g<->o. STS of h BEFORE the barrier, STG of out AFTER it.
__global__ void __launch_bounds__(128, 1)
lstm_kernel(const float* __restrict__ Whh, float* __restrict__ out) {
    __shared__ __align__(16) float hbuf[2][HD];

    int t    = blockIdx.x;
    int tid  = threadIdx.x;          // 128
    int odd  = tid & 1;
    int u    = tid >> 1;             // hidden unit 0..63
    int rowa = odd * 64 + u;         // i (even) / f (odd)  -> always sigmoid
    int rowb = 128 + odd * 64 + u;   // g (even) / o (odd)

    // row-b activation constants: tanh (even) / sigmoid (odd)
    float kb = odd ? 0.5f : 1.0f;
    float Ab = odd ? 0.5f : 1.0f;
    float Bb = odd ? 0.5f : 0.0f;

    // two W_hh rows pinned in registers as f32x2
    unsigned long long wa[32], wb[32];
    {
        const ulonglong2* pa = (const ulonglong2*)(Whh + (size_t)rowa * HD);
        const ulonglong2* pb = (const ulonglong2*)(Whh + (size_t)rowb * HD);
#pragma unroll
        for (int q = 0; q < 16; q++) {
            ulonglong2 va = __ldg(pa + q);
            ulonglong2 vb = __ldg(pb + q);
            wa[2*q] = va.x; wa[2*q+1] = va.y;
            wb[2*q] = vb.x; wb[2*q+1] = vb.y;
        }
    }

    if (tid < HD) hbuf[0][tid] = 0.0f;
    __syncthreads();

    float c = 0.0f;
    const float* gpa = g_gin + ((size_t)t * G4 + rowa) * NN;
    const float* gpb = g_gin + ((size_t)t * G4 + rowb) * NN;
    float* op = out + (size_t)t * NN * HD + u;

    float4 cura = __ldg((const float4*)gpa);
    float4 curb = __ldg((const float4*)gpb);
    float4 nxta = cura, nxtb = curb;

    for (int n0 = 0; n0 < NN; n0 += 4) {
        if (n0 + 4 < NN) {
            nxta = __ldg((const float4*)(gpa + n0 + 4));
            nxtb = __ldg((const float4*)(gpb + n0 + 4));
        }

#pragma unroll
        for (int s = 0; s < 4; s++) {
            int n = n0 + s;
            int b = s & 1;
            float gina = (s == 0) ? cura.x : (s == 1) ? cura.y : (s == 2) ? cura.z : cura.w;
            float ginb = (s == 0) ? curb.x : (s == 1) ? curb.y : (s == 2) ? curb.z : curb.w;

            // two dots sharing the h loads; 2 f32x2 chains per row
            unsigned long long a0 = pack2(gina, 0.0f), a1 = 0ull;
            unsigned long long b0 = pack2(ginb, 0.0f), b1 = 0ull;
            const ulonglong2* hv = (const ulonglong2*)&hbuf[b][0];
#pragma unroll
            for (int q = 0; q < 16; q++) {
                ulonglong2 p = hv[q];
                a0 = fma2(p.x, wa[2*q],     a0);
                a1 = fma2(p.y, wa[2*q + 1], a1);
                b0 = fma2(p.x, wb[2*q],     b0);
                b1 = fma2(p.y, wb[2*q + 1], b1);
            }
            float2 fa = unpack2(add2(a0, a1));
            float2 fb = unpack2(add2(b0, b1));
            float acc_a = fa.x + fa.y;
            float acc_b = fb.x + fb.y;

            // activations: one MUFU.TANH each
            float act_a = fmaf(0.5f, ftanh_hw(0.5f * acc_a), 0.5f);  // i (even) / f (odd)
            float act_b = fmaf(Ab,   ftanh_hw(kb * acc_b),   Bb);    // g (even) / o (odd)

            // product-exchange: even sends ig=i*g, odd sends f; plus o<->g swap
            float ig_l = act_a * act_b;                  // even: i*g (odd: f*o, unused)
            float sel  = odd ? act_a : ig_l;             // odd sends f, even sends ig
            float x1   = __shfl_xor_sync(0xffffffffu, sel,   1);
            float x2   = __shfl_xor_sync(0xffffffffu, act_b, 1);
            float f_   = odd ? act_a : x1;               // f in both threads
            float ig_  = odd ? x1    : ig_l;             // i*g in both threads
            float o_   = odd ? act_b : x2;               // o in both threads

            c = fmaf(f_, c, ig_);
            float h_ = o_ * ftanh_hw(c);

            if (!odd) hbuf[b ^ 1][u] = h_;   // STS first (recurrence-critical)
            __syncthreads();
            if (!odd) op[(size_t)n * HD] = h_;  // STG off the critical path
        }
        cura = nxta;
        curb = nxtb;
    }
}

// ---------------- launch ------------------------------------------------------
extern "C" void kernel_launch(void* const* d_in, const int* in_sizes, int n_in,
                              void* d_out, int out_size) {
    const float* x    = (const float*)d_in[0];
    const int*   ei   = (const int*)d_in[1];     // int32
    const float* Wg   = (const float*)d_in[2];
    const float* bg   = (const float*)d_in[3];
    const float* Wih  = (const float*)d_in[4];
    const float* Whh  = (const float*)d_in[5];
    const float* bih  = (const float*)d_in[6];
    const float* bhh  = (const float*)d_in[7];
    float*       out  = (float*)d_out;

    zero_dinv_kernel<<<(TT * NN + 255) / 256, 256>>>();
    count_xw_kernel <<<CNT_BLK + XW_BLK, 512>>>(ei, x, Wg);
    dinv_zero_kernel<<<DZ_BLK, 256>>>();
    scatter_kernel  <<<(TT * EE * 16) / 256, 256>>>(ei);
    gin_kernel      <<<TT * NN / 32, 256>>>(Wih, bg, bih, bhh);
    lstm_kernel     <<<TT, 128>>>(Whh, out);
}